// round 3
// baseline (speedup 1.0000x reference)
#include <cuda_runtime.h>
#include <math.h>

#define N_NODES  50000
#define N_EDGES  800000
#define N_GRAPHS 256
#define F        128

// ---------------- scratch (static __device__ — no allocation anywhere) ----------------
__device__ float g_buf0[N_NODES * F];
__device__ float g_buf1[N_NODES * F];
__device__ float g_dinv[N_NODES];
__device__ int   g_deg[N_NODES];
__device__ int   g_colptr[N_NODES + 1];
__device__ int   g_cursor[N_NODES];
__device__ int   g_csr[N_EDGES];
__device__ float g_concat[N_GRAPHS * 192];
__device__ float g_counts[N_GRAPHS];
__device__ float g_s0[N_GRAPHS * 256];
__device__ float g_s1[N_GRAPHS * 256];

// buffer selector resolved in DEVICE code (host never touches symbol addresses)
__device__ __forceinline__ float* gsel(int s) {
    switch (s) {
        case 0:  return g_buf0;
        case 1:  return g_buf1;
        case 2:  return g_concat;
        case 3:  return g_s0;
        default: return g_s1;
    }
}

// ---------------- init ----------------
__global__ void init_kernel() {
    int i = blockIdx.x * blockDim.x + threadIdx.x;
    if (i < N_NODES)        g_deg[i] = 0;
    if (i < N_GRAPHS)       g_counts[i] = 0.f;
    if (i < N_GRAPHS * 192) g_concat[i] = 0.f;
}

// ---------------- degree histogram (over col = destination) ----------------
__global__ void degree_kernel(const int* __restrict__ col) {
    int e = blockIdx.x * blockDim.x + threadIdx.x;
    if (e < N_EDGES) atomicAdd(&g_deg[col[e]], 1);
}

// ---------------- single-block exclusive scan -> colptr, cursor, dinv ----------------
__global__ void scan_kernel() {
    __shared__ int part[1024];
    int t = threadIdx.x;
    const int C = 49;  // ceil(50000/1024)
    int b = t * C;
    int e = min(b + C, N_NODES);
    int s = 0;
    for (int i = b; i < e; i++) s += g_deg[i];
    part[t] = s;
    __syncthreads();
    for (int off = 1; off < 1024; off <<= 1) {
        int v = (t >= off) ? part[t - off] : 0;
        __syncthreads();
        part[t] += v;
        __syncthreads();
    }
    int run = (t > 0) ? part[t - 1] : 0;
    for (int i = b; i < e; i++) {
        int d = g_deg[i];
        g_colptr[i] = run;
        g_cursor[i] = run;
        g_dinv[i]   = rsqrtf((float)d + 1.0f);
        run += d;
    }
    if (t == 1023) g_colptr[N_NODES] = part[1023];
}

// ---------------- CSR fill ----------------
__global__ void csr_fill_kernel(const int* __restrict__ row,
                                const int* __restrict__ col) {
    int e = blockIdx.x * blockDim.x + threadIdx.x;
    if (e < N_EDGES) {
        int c = col[e];
        int pos = atomicAdd(&g_cursor[c], 1);
        g_csr[pos] = row[e];
    }
}

// ---------------- per-graph node counts ----------------
__global__ void counts_kernel(const int* __restrict__ batch) {
    int n = blockIdx.x * blockDim.x + threadIdx.x;
    if (n < N_NODES) atomicAdd(&g_counts[batch[n]], 1.0f);
}

// ---------------- big GEMM: C[M,128] = A[M,128] @ W[128,128]^T (+ optional dinv/bias) -----
// tile 64M x 128N, 256 threads, TM=4 TN=8
__global__ __launch_bounds__(256)
void gemm128(const float* __restrict__ Aext, int aSel,
             const float* __restrict__ W, int cSel,
             const float* __restrict__ bias, int useDinv, int M) {
    const float* A = Aext ? Aext : gsel(aSel);
    float* C = gsel(cSel);

    __shared__ __align__(16) float As[64][33];
    __shared__ __align__(16) float Ws[32][132];
    int tid = threadIdx.x;
    int tx = tid & 15, ty = tid >> 4;
    int m0 = blockIdx.x * 64;

    float acc[4][8];
#pragma unroll
    for (int i = 0; i < 4; i++)
#pragma unroll
        for (int j = 0; j < 8; j++) acc[i][j] = 0.f;

    for (int kc = 0; kc < 128; kc += 32) {
#pragma unroll
        for (int j = 0; j < 8; j++) {
            int lin = j * 256 + tid;
            int m = lin >> 5, k = lin & 31;
            int gm = m0 + m;
            As[m][k] = (gm < M) ? A[gm * 128 + kc + k] : 0.f;
        }
#pragma unroll
        for (int j = 0; j < 16; j++) {
            int lin = j * 256 + tid;
            int n = lin >> 5, k = lin & 31;
            Ws[k][n] = W[n * 128 + kc + k];
        }
        __syncthreads();
#pragma unroll
        for (int k = 0; k < 32; k++) {
            float aa[4];
#pragma unroll
            for (int i = 0; i < 4; i++) aa[i] = As[ty * 4 + i][k];
            float4 b0 = *(const float4*)&Ws[k][tx * 8];
            float4 b1 = *(const float4*)&Ws[k][tx * 8 + 4];
            float bb[8] = {b0.x, b0.y, b0.z, b0.w, b1.x, b1.y, b1.z, b1.w};
#pragma unroll
            for (int i = 0; i < 4; i++)
#pragma unroll
                for (int j = 0; j < 8; j++) acc[i][j] += aa[i] * bb[j];
        }
        __syncthreads();
    }
#pragma unroll
    for (int i = 0; i < 4; i++) {
        int m = m0 + ty * 4 + i;
        if (m < M) {
            float rs = useDinv ? g_dinv[m] : 1.0f;
#pragma unroll
            for (int j = 0; j < 8; j++) {
                int n = tx * 8 + j;
                float v = acc[i][j] * rs;
                if (bias) v += bias[n];
                C[m * 128 + n] = v;
            }
        }
    }
}

// ---------------- CSR aggregation: out[i] = relu(dinv[i]*(sum_{j->i} g[j] + g[i]) + b) -----
__global__ __launch_bounds__(256)
void agg_kernel(int srcSel, int dstSel, const float* __restrict__ bias, int doRelu) {
    const float* g = gsel(srcSel);
    float* out = gsel(dstSel);
    int warp = (blockIdx.x * blockDim.x + threadIdx.x) >> 5;
    int lane = threadIdx.x & 31;
    if (warp >= N_NODES) return;
    int i = warp;
    int s = g_colptr[i], e = g_colptr[i + 1];
    const float4* g4 = (const float4*)g;

    float4 acc = g4[i * 32 + lane];  // self term
    int t = s;
    for (; t + 4 <= e; t += 4) {
        int j0 = g_csr[t], j1 = g_csr[t + 1], j2 = g_csr[t + 2], j3 = g_csr[t + 3];
        float4 v0 = g4[j0 * 32 + lane];
        float4 v1 = g4[j1 * 32 + lane];
        float4 v2 = g4[j2 * 32 + lane];
        float4 v3 = g4[j3 * 32 + lane];
        acc.x += v0.x + v1.x + v2.x + v3.x;
        acc.y += v0.y + v1.y + v2.y + v3.y;
        acc.z += v0.z + v1.z + v2.z + v3.z;
        acc.w += v0.w + v1.w + v2.w + v3.w;
    }
    for (; t < e; t++) {
        int j = g_csr[t];
        float4 v = g4[j * 32 + lane];
        acc.x += v.x; acc.y += v.y; acc.z += v.z; acc.w += v.w;
    }
    float di = g_dinv[i];
    float4 b4 = *(const float4*)&bias[lane * 4];
    acc.x = acc.x * di + b4.x;
    acc.y = acc.y * di + b4.y;
    acc.z = acc.z * di + b4.z;
    acc.w = acc.w * di + b4.w;
    if (doRelu) {
        acc.x = fmaxf(acc.x, 0.f); acc.y = fmaxf(acc.y, 0.f);
        acc.z = fmaxf(acc.z, 0.f); acc.w = fmaxf(acc.w, 0.f);
    }
    ((float4*)out)[i * 32 + lane] = acc;
}

// ---------------- pooling: chunked segment-sum (sorted batch_index) ----------------
__global__ void pool_kernel(const int* __restrict__ batch) {
    const float* h = g_buf0;
    int c = threadIdx.x;         // feature 0..127
    int n0 = blockIdx.x * 256;
    int nend = min(n0 + 256, N_NODES);
    int cur = -1;
    float acc = 0.f;
    for (int n = n0; n < nend; n++) {
        int b = batch[n];
        if (b != cur) {
            if (cur >= 0) atomicAdd(&g_concat[cur * 192 + c], acc);
            cur = b;
            acc = 0.f;
        }
        acc += h[n * F + c];
    }
    if (cur >= 0) atomicAdd(&g_concat[cur * 192 + c], acc);
}

__global__ void divide_kernel() {
    int i = blockIdx.x * blockDim.x + threadIdx.x;
    if (i < N_GRAPHS * F) {
        int gg = i >> 7, c = i & 127;
        g_concat[gg * 192 + c] /= fmaxf(g_counts[gg], 1.0f);
    }
}

// ---------------- generic small GEMM: C[M,N] = act(A[M,K] @ W[N,K]^T + b) ----------------
// tile 64x64, 256 threads; K multiple of 32 (true for all calls: 256, 192)
__global__ __launch_bounds__(256)
void small_gemm(const float* __restrict__ Aext, int aSel, int aOff, int lda,
                const float* __restrict__ W, const float* __restrict__ bias,
                float* __restrict__ Cext, int cSel, int cOff, int ldc,
                int M, int N, int K, int doRelu) {
    const float* A = (Aext ? Aext : gsel(aSel) + aOff);
    float* C = (Cext ? Cext : gsel(cSel) + cOff);

    __shared__ __align__(16) float As[64][33];
    __shared__ __align__(16) float Ws[32][68];
    int tid = threadIdx.x;
    int tx = tid & 15, ty = tid >> 4;
    int n0 = blockIdx.x * 64, m0 = blockIdx.y * 64;

    float acc[4][4];
#pragma unroll
    for (int i = 0; i < 4; i++)
#pragma unroll
        for (int j = 0; j < 4; j++) acc[i][j] = 0.f;

    for (int kc = 0; kc < K; kc += 32) {
#pragma unroll
        for (int j = 0; j < 8; j++) {
            int lin = j * 256 + tid;
            int m = lin >> 5, k = lin & 31;
            As[m][k] = (m0 + m < M) ? A[(m0 + m) * lda + kc + k] : 0.f;
        }
#pragma unroll
        for (int j = 0; j < 8; j++) {
            int lin = j * 256 + tid;
            int n = lin >> 5, k = lin & 31;
            Ws[k][n] = (n0 + n < N) ? W[(n0 + n) * K + kc + k] : 0.f;
        }
        __syncthreads();
#pragma unroll
        for (int k = 0; k < 32; k++) {
            float aa[4];
#pragma unroll
            for (int i = 0; i < 4; i++) aa[i] = As[ty * 4 + i][k];
            float4 b = *(const float4*)&Ws[k][tx * 4];
            float bb[4] = {b.x, b.y, b.z, b.w};
#pragma unroll
            for (int i = 0; i < 4; i++)
#pragma unroll
                for (int j = 0; j < 4; j++) acc[i][j] += aa[i] * bb[j];
        }
        __syncthreads();
    }
#pragma unroll
    for (int i = 0; i < 4; i++) {
        int m = m0 + ty * 4 + i;
        if (m < M) {
#pragma unroll
            for (int j = 0; j < 4; j++) {
                int n = n0 + tx * 4 + j;
                if (n < N) {
                    float v = acc[i][j];
                    if (bias) v += bias[n];
                    if (doRelu) v = fmaxf(v, 0.f);
                    C[m * ldc + n] = v;
                }
            }
        }
    }
}

// ---------------- launch ----------------
extern "C" void kernel_launch(void* const* d_in, const int* in_sizes, int n_in,
                              void* d_out, int out_size) {
    const float* x         = (const float*)d_in[0];
    const int*   ei        = (const int*)d_in[1];     // int32 (JAX x64 disabled)
    const int*   batch     = (const int*)d_in[2];     // int32
    const float* mol       = (const float*)d_in[3];
    const float* gcn_W     = (const float*)d_in[4];
    const float* gcn_b     = (const float*)d_in[5];
    const float* gcn_out_W = (const float*)d_in[6];
    const float* gcn_out_b = (const float*)d_in[7];
    const float* mlp_W     = (const float*)d_in[8];
    const float* mlp_b     = (const float*)d_in[9];
    const float* mlp_out_W = (const float*)d_in[10];
    const float* mlp_out_b = (const float*)d_in[11];
    const float* pred_W1   = (const float*)d_in[12];
    const float* pred_b1   = (const float*)d_in[13];
    const float* pred_W2   = (const float*)d_in[14];
    const float* pred_b2   = (const float*)d_in[15];
    const float* out_W     = (const float*)d_in[16];
    const float* out_b     = (const float*)d_in[17];
    float* out = (float*)d_out;

    // graph preprocessing (reused by all 3 GCN layers)
    init_kernel<<<196, 256>>>();
    degree_kernel<<<3125, 256>>>(ei + N_EDGES);
    scan_kernel<<<1, 1024>>>();
    csr_fill_kernel<<<3125, 256>>>(ei, ei + N_EDGES);
    counts_kernel<<<196, 256>>>(batch);

    const int GB = (N_NODES + 63) / 64;         // 782
    const int AB = (N_NODES * 32 + 255) / 256;  // 6250

    // GCN layer i: g = (h @ W^T) * dinv (in gemm epilogue);
    //              h' = relu(dinv*(csr_sum(g)+g) + b)   [agg kernel]
    gemm128<<<GB, 256>>>(x,       -1, gcn_W,                 0, nullptr, 1, N_NODES);
    agg_kernel<<<AB, 256>>>(0, 1, gcn_b, 1);
    gemm128<<<GB, 256>>>(nullptr,  1, gcn_W + 128 * 128,     0, nullptr, 1, N_NODES);
    agg_kernel<<<AB, 256>>>(0, 1, gcn_b + 128, 1);
    gemm128<<<GB, 256>>>(nullptr,  1, gcn_W + 2 * 128 * 128, 0, nullptr, 1, N_NODES);
    agg_kernel<<<AB, 256>>>(0, 1, gcn_b + 256, 1);
    // final GCN linear (bias, no relu, no dinv) -> buf0
    gemm128<<<GB, 256>>>(nullptr,  1, gcn_out_W,             0, gcn_out_b, 0, N_NODES);

    // mean pool -> g_concat[:, 0:128]
    pool_kernel<<<196, 128>>>(batch);
    divide_kernel<<<128, 256>>>();

    // MLP branch -> g_concat[:, 128:192]   (sel: 2=concat, 3=s0, 4=s1)
    small_gemm<<<dim3(4, 4), 256>>>(mol, -1, 0, 256, mlp_W,         mlp_b,       nullptr, 3, 0, 256, 256, 256, 256, 1);
    small_gemm<<<dim3(4, 4), 256>>>(nullptr, 3, 0, 256, mlp_W + 65536, mlp_b + 256, nullptr, 4, 0, 256, 256, 256, 256, 1);
    small_gemm<<<dim3(1, 4), 256>>>(nullptr, 4, 0, 256, mlp_out_W,  mlp_out_b,   nullptr, 2, 128, 192, 256, 64, 256, 1);

    // prediction head
    small_gemm<<<dim3(4, 4), 256>>>(nullptr, 2, 0, 192, pred_W1, pred_b1, nullptr, 3, 0, 256, 256, 256, 192, 1);
    small_gemm<<<dim3(4, 4), 256>>>(nullptr, 3, 0, 256, pred_W2, pred_b2, nullptr, 4, 0, 256, 256, 256, 256, 1);
    small_gemm<<<dim3(1, 4), 256>>>(nullptr, 4, 0, 256, out_W,   out_b,   out,     0, 0, 1,   256, 1,   256, 0);
}

// round 4
// speedup vs baseline: 1.0376x; 1.0376x over previous
#include <cuda_runtime.h>
#include <math.h>
#include <stdint.h>

#define N_NODES  50000
#define N_EDGES  800000
#define N_GRAPHS 256
#define F        128

// ---------------- scratch (static __device__ — no allocation anywhere) ----------------
__device__ float g_buf0[N_NODES * F];
__device__ float g_buf1[N_NODES * F];
__device__ float g_dinv[N_NODES];
__device__ int   g_deg[N_NODES];
__device__ int   g_colptr[N_NODES + 1];
__device__ int   g_cursor[N_NODES];
__device__ int   g_csr[N_EDGES];
__device__ float g_concat[N_GRAPHS * 192];
__device__ float g_counts[N_GRAPHS];
__device__ float g_s0[N_GRAPHS * 256];
__device__ float g_s1[N_GRAPHS * 256];

// buffer selector resolved in DEVICE code (host never touches symbol addresses)
__device__ __forceinline__ float* gsel(int s) {
    switch (s) {
        case 0:  return g_buf0;
        case 1:  return g_buf1;
        case 2:  return g_concat;
        case 3:  return g_s0;
        default: return g_s1;
    }
}

// ---------------- init ----------------
__global__ void init_kernel() {
    int i = blockIdx.x * blockDim.x + threadIdx.x;
    if (i < N_NODES)        g_deg[i] = 0;
    if (i < N_GRAPHS)       g_counts[i] = 0.f;
    if (i < N_GRAPHS * 192) g_concat[i] = 0.f;
}

// ---------------- degree histogram (over col = destination) ----------------
__global__ void degree_kernel(const int* __restrict__ col) {
    int e = blockIdx.x * blockDim.x + threadIdx.x;
    if (e < N_EDGES) atomicAdd(&g_deg[col[e]], 1);
}

// ---------------- single-block exclusive scan -> colptr, cursor, dinv ----------------
__global__ void scan_kernel() {
    __shared__ int part[1024];
    int t = threadIdx.x;
    const int C = 49;  // ceil(50000/1024)
    int b = t * C;
    int e = min(b + C, N_NODES);
    int s = 0;
    for (int i = b; i < e; i++) s += g_deg[i];
    part[t] = s;
    __syncthreads();
    for (int off = 1; off < 1024; off <<= 1) {
        int v = (t >= off) ? part[t - off] : 0;
        __syncthreads();
        part[t] += v;
        __syncthreads();
    }
    int run = (t > 0) ? part[t - 1] : 0;
    for (int i = b; i < e; i++) {
        int d = g_deg[i];
        g_colptr[i] = run;
        g_cursor[i] = run;
        g_dinv[i]   = rsqrtf((float)d + 1.0f);
        run += d;
    }
    if (t == 1023) g_colptr[N_NODES] = part[1023];
}

// ---------------- CSR fill ----------------
__global__ void csr_fill_kernel(const int* __restrict__ row,
                                const int* __restrict__ col) {
    int e = blockIdx.x * blockDim.x + threadIdx.x;
    if (e < N_EDGES) {
        int c = col[e];
        int pos = atomicAdd(&g_cursor[c], 1);
        g_csr[pos] = row[e];
    }
}

// ---------------- per-graph node counts ----------------
__global__ void counts_kernel(const int* __restrict__ batch) {
    int n = blockIdx.x * blockDim.x + threadIdx.x;
    if (n < N_NODES) atomicAdd(&g_counts[batch[n]], 1.0f);
}

// ---------------- tf32 helpers ----------------
__device__ __forceinline__ uint32_t f2tf32(float f) {
    uint32_t r;
    asm("cvt.rna.tf32.f32 %0, %1;" : "=r"(r) : "f"(f));
    return r;
}

__device__ __forceinline__ void mma_tf32(float (&c)[4], const uint32_t (&a)[4],
                                         uint32_t b0, uint32_t b1) {
    asm("mma.sync.aligned.m16n8k8.row.col.f32.tf32.tf32.f32 "
        "{%0,%1,%2,%3},{%4,%5,%6,%7},{%8,%9},{%0,%1,%2,%3};"
        : "+f"(c[0]), "+f"(c[1]), "+f"(c[2]), "+f"(c[3])
        : "r"(a[0]), "r"(a[1]), "r"(a[2]), "r"(a[3]), "r"(b0), "r"(b1));
}

// ---------------- tensor-core GEMM: C[M,128] = A[M,128] @ W[128,128]^T -----------------
// block tile 128M x 128N, 8 warps (4Mx2N), warp tile 32x64, K chunks of 64
// smem: As[128][68], Ws[128][68] (n-major, k inner), tf32-converted
#define KPAD 68
__global__ __launch_bounds__(256)
void gemm_tf32(const float* __restrict__ Aext, int aSel,
               const float* __restrict__ W, int cSel,
               const float* __restrict__ bias, int useDinv, int M) {
    extern __shared__ uint32_t sm[];
    uint32_t* As = sm;                 // [128][KPAD]
    uint32_t* Ws = sm + 128 * KPAD;    // [128][KPAD]
    const float* A = Aext ? Aext : gsel(aSel);
    float* C = gsel(cSel);

    int tid = threadIdx.x;
    int wid = tid >> 5, lane = tid & 31;
    int group = lane >> 2, tig = lane & 3;
    int warpM = wid & 3, warpN = wid >> 2;
    int m0 = blockIdx.x * 128;

    float acc[2][8][4];
#pragma unroll
    for (int mt = 0; mt < 2; mt++)
#pragma unroll
        for (int nt = 0; nt < 8; nt++)
#pragma unroll
            for (int i = 0; i < 4; i++) acc[mt][nt][i] = 0.f;

    for (int kc = 0; kc < 128; kc += 64) {
        __syncthreads();
        // A chunk: 128 rows x 64 cols -> 2048 float4, 8 per thread
#pragma unroll
        for (int i = 0; i < 8; i++) {
            int lin = i * 256 + tid;
            int r = lin >> 4;           // 16 float4 per row
            int c = (lin & 15) * 4;
            float4 v = make_float4(0.f, 0.f, 0.f, 0.f);
            if (m0 + r < M) v = *(const float4*)&A[(m0 + r) * 128 + kc + c];
            uint4 t;
            t.x = f2tf32(v.x); t.y = f2tf32(v.y);
            t.z = f2tf32(v.z); t.w = f2tf32(v.w);
            *(uint4*)&As[r * KPAD + c] = t;
        }
        // W chunk: Ws[n][k] = W[n*128 + kc + k]
#pragma unroll
        for (int i = 0; i < 8; i++) {
            int lin = i * 256 + tid;
            int n = lin >> 4;
            int c = (lin & 15) * 4;
            float4 v = *(const float4*)&W[n * 128 + kc + c];
            uint4 t;
            t.x = f2tf32(v.x); t.y = f2tf32(v.y);
            t.z = f2tf32(v.z); t.w = f2tf32(v.w);
            *(uint4*)&Ws[n * KPAD + c] = t;
        }
        __syncthreads();
#pragma unroll
        for (int ks = 0; ks < 8; ks++) {
            int k0 = ks * 8;
            uint32_t a[2][4];
#pragma unroll
            for (int mt = 0; mt < 2; mt++) {
                int r = warpM * 32 + mt * 16 + group;
                a[mt][0] = As[r * KPAD + k0 + tig];
                a[mt][1] = As[(r + 8) * KPAD + k0 + tig];
                a[mt][2] = As[r * KPAD + k0 + tig + 4];
                a[mt][3] = As[(r + 8) * KPAD + k0 + tig + 4];
            }
#pragma unroll
            for (int nt = 0; nt < 8; nt++) {
                int n = warpN * 64 + nt * 8 + group;
                uint32_t b0 = Ws[n * KPAD + k0 + tig];
                uint32_t b1 = Ws[n * KPAD + k0 + tig + 4];
                mma_tf32(acc[0][nt], a[0], b0, b1);
                mma_tf32(acc[1][nt], a[1], b0, b1);
            }
        }
    }
    // epilogue: c0,c1 -> (row=group, cols 2*tig,2*tig+1); c2,c3 -> row=group+8
#pragma unroll
    for (int mt = 0; mt < 2; mt++) {
#pragma unroll
        for (int half = 0; half < 2; half++) {
            int m = m0 + warpM * 32 + mt * 16 + group + half * 8;
            if (m < M) {
                float rs = useDinv ? g_dinv[m] : 1.0f;
#pragma unroll
                for (int nt = 0; nt < 8; nt++) {
                    int n = warpN * 64 + nt * 8 + tig * 2;
                    float v0 = acc[mt][nt][half * 2 + 0] * rs;
                    float v1 = acc[mt][nt][half * 2 + 1] * rs;
                    if (bias) { v0 += bias[n]; v1 += bias[n + 1]; }
                    *(float2*)&C[m * 128 + n] = make_float2(v0, v1);
                }
            }
        }
    }
}
#define GEMM_SMEM (2 * 128 * KPAD * 4)

// ---------------- CSR aggregation: out[i] = relu(dinv[i]*(sum_{j->i} g[j] + g[i]) + b) -----
__global__ __launch_bounds__(256)
void agg_kernel(int srcSel, int dstSel, const float* __restrict__ bias, int doRelu) {
    const float* g = gsel(srcSel);
    float* out = gsel(dstSel);
    int warp = (blockIdx.x * blockDim.x + threadIdx.x) >> 5;
    int lane = threadIdx.x & 31;
    if (warp >= N_NODES) return;
    int i = warp;
    int s = g_colptr[i], e = g_colptr[i + 1];
    const float4* g4 = (const float4*)g;

    float4 acc = g4[i * 32 + lane];  // self term
    int t = s;
    for (; t + 4 <= e; t += 4) {
        int j0 = g_csr[t], j1 = g_csr[t + 1], j2 = g_csr[t + 2], j3 = g_csr[t + 3];
        float4 v0 = g4[j0 * 32 + lane];
        float4 v1 = g4[j1 * 32 + lane];
        float4 v2 = g4[j2 * 32 + lane];
        float4 v3 = g4[j3 * 32 + lane];
        acc.x += v0.x + v1.x + v2.x + v3.x;
        acc.y += v0.y + v1.y + v2.y + v3.y;
        acc.z += v0.z + v1.z + v2.z + v3.z;
        acc.w += v0.w + v1.w + v2.w + v3.w;
    }
    for (; t < e; t++) {
        int j = g_csr[t];
        float4 v = g4[j * 32 + lane];
        acc.x += v.x; acc.y += v.y; acc.z += v.z; acc.w += v.w;
    }
    float di = g_dinv[i];
    float4 b4 = *(const float4*)&bias[lane * 4];
    acc.x = acc.x * di + b4.x;
    acc.y = acc.y * di + b4.y;
    acc.z = acc.z * di + b4.z;
    acc.w = acc.w * di + b4.w;
    if (doRelu) {
        acc.x = fmaxf(acc.x, 0.f); acc.y = fmaxf(acc.y, 0.f);
        acc.z = fmaxf(acc.z, 0.f); acc.w = fmaxf(acc.w, 0.f);
    }
    ((float4*)out)[i * 32 + lane] = acc;
}

// ---------------- pooling: chunked segment-sum (sorted batch_index) ----------------
__global__ void pool_kernel(const int* __restrict__ batch) {
    const float* h = g_buf0;
    int c = threadIdx.x;         // feature 0..127
    int n0 = blockIdx.x * 256;
    int nend = min(n0 + 256, N_NODES);
    int cur = -1;
    float acc = 0.f;
    for (int n = n0; n < nend; n++) {
        int b = batch[n];
        if (b != cur) {
            if (cur >= 0) atomicAdd(&g_concat[cur * 192 + c], acc);
            cur = b;
            acc = 0.f;
        }
        acc += h[n * F + c];
    }
    if (cur >= 0) atomicAdd(&g_concat[cur * 192 + c], acc);
}

__global__ void divide_kernel() {
    int i = blockIdx.x * blockDim.x + threadIdx.x;
    if (i < N_GRAPHS * F) {
        int gg = i >> 7, c = i & 127;
        g_concat[gg * 192 + c] /= fmaxf(g_counts[gg], 1.0f);
    }
}

// ---------------- generic small GEMM: C[M,N] = act(A[M,K] @ W[N,K]^T + b) ----------------
__global__ __launch_bounds__(256)
void small_gemm(const float* __restrict__ Aext, int aSel, int aOff, int lda,
                const float* __restrict__ W, const float* __restrict__ bias,
                float* __restrict__ Cext, int cSel, int cOff, int ldc,
                int M, int N, int K, int doRelu) {
    const float* A = (Aext ? Aext : gsel(aSel) + aOff);
    float* C = (Cext ? Cext : gsel(cSel) + cOff);

    __shared__ __align__(16) float As[64][33];
    __shared__ __align__(16) float Ws[32][68];
    int tid = threadIdx.x;
    int tx = tid & 15, ty = tid >> 4;
    int n0 = blockIdx.x * 64, m0 = blockIdx.y * 64;

    float acc[4][4];
#pragma unroll
    for (int i = 0; i < 4; i++)
#pragma unroll
        for (int j = 0; j < 4; j++) acc[i][j] = 0.f;

    for (int kc = 0; kc < K; kc += 32) {
#pragma unroll
        for (int j = 0; j < 8; j++) {
            int lin = j * 256 + tid;
            int m = lin >> 5, k = lin & 31;
            As[m][k] = (m0 + m < M) ? A[(m0 + m) * lda + kc + k] : 0.f;
        }
#pragma unroll
        for (int j = 0; j < 8; j++) {
            int lin = j * 256 + tid;
            int n = lin >> 5, k = lin & 31;
            Ws[k][n] = (n0 + n < N) ? W[(n0 + n) * K + kc + k] : 0.f;
        }
        __syncthreads();
#pragma unroll
        for (int k = 0; k < 32; k++) {
            float aa[4];
#pragma unroll
            for (int i = 0; i < 4; i++) aa[i] = As[ty * 4 + i][k];
            float4 b = *(const float4*)&Ws[k][tx * 4];
            float bb[4] = {b.x, b.y, b.z, b.w};
#pragma unroll
            for (int i = 0; i < 4; i++)
#pragma unroll
                for (int j = 0; j < 4; j++) acc[i][j] += aa[i] * bb[j];
        }
        __syncthreads();
    }
#pragma unroll
    for (int i = 0; i < 4; i++) {
        int m = m0 + ty * 4 + i;
        if (m < M) {
#pragma unroll
            for (int j = 0; j < 4; j++) {
                int n = n0 + tx * 4 + j;
                if (n < N) {
                    float v = acc[i][j];
                    if (bias) v += bias[n];
                    if (doRelu) v = fmaxf(v, 0.f);
                    C[m * ldc + n] = v;
                }
            }
        }
    }
}

// ---------------- launch ----------------
extern "C" void kernel_launch(void* const* d_in, const int* in_sizes, int n_in,
                              void* d_out, int out_size) {
    const float* x         = (const float*)d_in[0];
    const int*   ei        = (const int*)d_in[1];
    const int*   batch     = (const int*)d_in[2];
    const float* mol       = (const float*)d_in[3];
    const float* gcn_W     = (const float*)d_in[4];
    const float* gcn_b     = (const float*)d_in[5];
    const float* gcn_out_W = (const float*)d_in[6];
    const float* gcn_out_b = (const float*)d_in[7];
    const float* mlp_W     = (const float*)d_in[8];
    const float* mlp_b     = (const float*)d_in[9];
    const float* mlp_out_W = (const float*)d_in[10];
    const float* mlp_out_b = (const float*)d_in[11];
    const float* pred_W1   = (const float*)d_in[12];
    const float* pred_b1   = (const float*)d_in[13];
    const float* pred_W2   = (const float*)d_in[14];
    const float* pred_b2   = (const float*)d_in[15];
    const float* out_W     = (const float*)d_in[16];
    const float* out_b     = (const float*)d_in[17];
    float* out = (float*)d_out;

    cudaFuncSetAttribute(gemm_tf32, cudaFuncAttributeMaxDynamicSharedMemorySize, GEMM_SMEM);

    // graph preprocessing (reused by all 3 GCN layers)
    init_kernel<<<196, 256>>>();
    degree_kernel<<<3125, 256>>>(ei + N_EDGES);
    scan_kernel<<<1, 1024>>>();
    csr_fill_kernel<<<3125, 256>>>(ei, ei + N_EDGES);
    counts_kernel<<<196, 256>>>(batch);

    const int GB = (N_NODES + 127) / 128;       // 391
    const int AB = (N_NODES * 32 + 255) / 256;  // 6250

    // GCN layer i: g = (h @ W^T) * dinv (gemm epilogue); h' = relu(dinv*(csr_sum(g)+g)+b)
    gemm_tf32<<<GB, 256, GEMM_SMEM>>>(x,       -1, gcn_W,                 0, nullptr, 1, N_NODES);
    agg_kernel<<<AB, 256>>>(0, 1, gcn_b, 1);
    gemm_tf32<<<GB, 256, GEMM_SMEM>>>(nullptr,  1, gcn_W + 128 * 128,     0, nullptr, 1, N_NODES);
    agg_kernel<<<AB, 256>>>(0, 1, gcn_b + 128, 1);
    gemm_tf32<<<GB, 256, GEMM_SMEM>>>(nullptr,  1, gcn_W + 2 * 128 * 128, 0, nullptr, 1, N_NODES);
    agg_kernel<<<AB, 256>>>(0, 1, gcn_b + 256, 1);
    // final GCN linear (bias, no relu, no dinv) -> buf0
    gemm_tf32<<<GB, 256, GEMM_SMEM>>>(nullptr,  1, gcn_out_W,             0, gcn_out_b, 0, N_NODES);

    // mean pool -> g_concat[:, 0:128]
    pool_kernel<<<196, 128>>>(batch);
    divide_kernel<<<128, 256>>>();

    // MLP branch -> g_concat[:, 128:192]   (sel: 2=concat, 3=s0, 4=s1)
    small_gemm<<<dim3(4, 4), 256>>>(mol, -1, 0, 256, mlp_W,         mlp_b,       nullptr, 3, 0, 256, 256, 256, 256, 1);
    small_gemm<<<dim3(4, 4), 256>>>(nullptr, 3, 0, 256, mlp_W + 65536, mlp_b + 256, nullptr, 4, 0, 256, 256, 256, 256, 1);
    small_gemm<<<dim3(1, 4), 256>>>(nullptr, 4, 0, 256, mlp_out_W,  mlp_out_b,   nullptr, 2, 128, 192, 256, 64, 256, 1);

    // prediction head
    small_gemm<<<dim3(4, 4), 256>>>(nullptr, 2, 0, 192, pred_W1, pred_b1, nullptr, 3, 0, 256, 256, 256, 192, 1);
    small_gemm<<<dim3(4, 4), 256>>>(nullptr, 3, 0, 256, pred_W2, pred_b2, nullptr, 4, 0, 256, 256, 256, 256, 1);
    small_gemm<<<dim3(1, 4), 256>>>(nullptr, 4, 0, 256, out_W,   out_b,   out,     0, 0, 1,   256, 1,   256, 0);
}

// round 5
// speedup vs baseline: 2.7468x; 2.6473x over previous
#include <cuda_runtime.h>
#include <cuda_fp16.h>
#include <math.h>
#include <stdint.h>

#define N_NODES  50000
#define N_EDGES  800000
#define N_GRAPHS 256
#define F        128
#define NB       256   // scan blocks
#define CH       196   // nodes per scan block (256*196 >= 50000)

// ---------------- scratch (static __device__ — no allocation anywhere) ----------------
__device__ __half g_h0[N_NODES * F];
__device__ __half g_h1[N_NODES * F];
__device__ float  g_dinv[N_NODES];
__device__ int    g_deg[N_NODES];
__device__ int    g_colptr[N_NODES + 1];
__device__ int    g_cursor[N_NODES];
__device__ int    g_csr[N_EDGES];
__device__ int    g_part[NB];
__device__ int    g_poff[NB];
__device__ int    g_counti[N_GRAPHS];
__device__ int    g_gstart[N_GRAPHS + 1];
__device__ float  g_concat[N_GRAPHS * 192];
__device__ float  g_s0[N_GRAPHS * 256];
__device__ float  g_s1[N_GRAPHS * 256];

__device__ __forceinline__ __half* hsel(int s) { return s == 0 ? g_h0 : g_h1; }
__device__ __forceinline__ float* fsel(int s) {
    switch (s) { case 2: return g_concat; case 3: return g_s0; default: return g_s1; }
}

// ---------------- init ----------------
__global__ void init_kernel() {
    int i = blockIdx.x * blockDim.x + threadIdx.x;
    if (i < N_NODES)  g_deg[i] = 0;
    if (i < N_GRAPHS) g_counti[i] = 0;
}

// ---------------- degree histogram (over col = destination) ----------------
__global__ void degree_kernel(const int* __restrict__ col) {
    int e = blockIdx.x * blockDim.x + threadIdx.x;
    if (e < N_EDGES) atomicAdd(&g_deg[col[e]], 1);
}

// ---------------- dinv from degree ----------------
__global__ void dinv_kernel() {
    int i = blockIdx.x * blockDim.x + threadIdx.x;
    if (i < N_NODES) g_dinv[i] = rsqrtf((float)g_deg[i] + 1.0f);
}

// ---------------- 3-phase parallel scan of degrees -> colptr/cursor ----------------
__global__ void scanA_kernel() {           // per-block partial sums
    __shared__ int s[256];
    int t = threadIdx.x, b = blockIdx.x;
    int i = b * CH + t;
    int v = (t < CH && i < N_NODES) ? g_deg[i] : 0;
    s[t] = v;
    __syncthreads();
    for (int off = 128; off > 0; off >>= 1) {
        if (t < off) s[t] += s[t + off];
        __syncthreads();
    }
    if (t == 0) g_part[b] = s[0];
}
__global__ void scanB_kernel() {           // scan the 256 partials
    __shared__ int s[NB];
    int t = threadIdx.x;
    int mine = g_part[t];
    s[t] = mine;
    __syncthreads();
    for (int off = 1; off < NB; off <<= 1) {
        int v = (t >= off) ? s[t - off] : 0;
        __syncthreads();
        s[t] += v;
        __syncthreads();
    }
    g_poff[t] = s[t] - mine;               // exclusive
    if (t == 0) g_colptr[N_NODES] = N_EDGES;
}
__global__ void scanC_kernel() {           // per-block exclusive scan + offset
    __shared__ int s[256];
    int t = threadIdx.x, b = blockIdx.x;
    int i = b * CH + t;
    int d = (t < CH && i < N_NODES) ? g_deg[i] : 0;
    s[t] = d;
    __syncthreads();
    for (int off = 1; off < 256; off <<= 1) {
        int v = (t >= off) ? s[t - off] : 0;
        __syncthreads();
        s[t] += v;
        __syncthreads();
    }
    if (t < CH && i < N_NODES) {
        int cp = g_poff[b] + s[t] - d;
        g_colptr[i] = cp;
        g_cursor[i] = cp;
    }
}

// ---------------- CSR fill ----------------
__global__ void csr_fill_kernel(const int* __restrict__ row,
                                const int* __restrict__ col) {
    int e = blockIdx.x * blockDim.x + threadIdx.x;
    if (e < N_EDGES) {
        int c = col[e];
        int pos = atomicAdd(&g_cursor[c], 1);
        g_csr[pos] = row[e];
    }
}

// ---------------- per-graph node counts + boundaries ----------------
__global__ void counts_kernel(const int* __restrict__ batch) {
    int n = blockIdx.x * blockDim.x + threadIdx.x;
    if (n < N_NODES) atomicAdd(&g_counti[batch[n]], 1);
}
__global__ void gstart_kernel() {          // 1 block, 256 threads
    __shared__ int s[N_GRAPHS];
    int t = threadIdx.x;
    s[t] = g_counti[t];
    __syncthreads();
    for (int off = 1; off < N_GRAPHS; off <<= 1) {
        int v = (t >= off) ? s[t - off] : 0;
        __syncthreads();
        s[t] += v;
        __syncthreads();
    }
    g_gstart[t + 1] = s[t];
    if (t == 0) g_gstart[0] = 0;
}

// ---------------- fp16 MMA helpers ----------------
__device__ __forceinline__ void mma_f16(float (&c)[4], const uint32_t (&a)[4],
                                        uint32_t b0, uint32_t b1) {
    asm("mma.sync.aligned.m16n8k16.row.col.f32.f16.f16.f32 "
        "{%0,%1,%2,%3},{%4,%5,%6,%7},{%8,%9},{%0,%1,%2,%3};"
        : "+f"(c[0]), "+f"(c[1]), "+f"(c[2]), "+f"(c[3])
        : "r"(a[0]), "r"(a[1]), "r"(a[2]), "r"(a[3]), "r"(b0), "r"(b1));
}

// ---------------- fp16 tensor-core GEMM: C[M,128] = A[M,128] @ W[128,128]^T -------------
// block tile 128Mx128N, 8 warps (4Mx2N), warp tile 32x64, full K=128 staged once.
// smem halves, stride HS=136 (conflict-free fragment loads: g*68+t distinct mod 32).
#define HS 136
#define GEMM_SMEM (2 * 128 * HS * 2)
__global__ __launch_bounds__(256)
void gemm_f16(const float* __restrict__ Aext, int aSel,
              const float* __restrict__ W, int cSel,
              const float* __restrict__ bias, int useDinv, int M) {
    extern __shared__ __half sh[];
    __half* As = sh;              // [128][HS]
    __half* Ws = sh + 128 * HS;   // [128][HS]
    __half* C = hsel(cSel);

    int tid = threadIdx.x;
    int wid = tid >> 5, lane = tid & 31;
    int group = lane >> 2, tig = lane & 3;
    int warpM = wid & 3, warpN = wid >> 2;
    int m0 = blockIdx.x * 128;

    // fill A: 128 rows x 128 halves = 2048 x 8-half chunks, 8 per thread
    if (Aext) {
#pragma unroll
        for (int i = 0; i < 8; i++) {
            int lin = i * 256 + tid;
            int r = lin >> 4, c = (lin & 15) * 8;
            float4 v0 = make_float4(0.f, 0.f, 0.f, 0.f), v1 = v0;
            if (m0 + r < M) {
                v0 = *(const float4*)&Aext[(m0 + r) * 128 + c];
                v1 = *(const float4*)&Aext[(m0 + r) * 128 + c + 4];
            }
            __half2 h0 = __floats2half2_rn(v0.x, v0.y);
            __half2 h1 = __floats2half2_rn(v0.z, v0.w);
            __half2 h2 = __floats2half2_rn(v1.x, v1.y);
            __half2 h3 = __floats2half2_rn(v1.z, v1.w);
            uint4 t;
            t.x = *(uint32_t*)&h0; t.y = *(uint32_t*)&h1;
            t.z = *(uint32_t*)&h2; t.w = *(uint32_t*)&h3;
            *(uint4*)&As[r * HS + c] = t;
        }
    } else {
        const __half* A = hsel(aSel);
#pragma unroll
        for (int i = 0; i < 8; i++) {
            int lin = i * 256 + tid;
            int r = lin >> 4, c = (lin & 15) * 8;
            uint4 t = make_uint4(0, 0, 0, 0);
            if (m0 + r < M) t = *(const uint4*)&A[(m0 + r) * 128 + c];
            *(uint4*)&As[r * HS + c] = t;
        }
    }
    // fill W (fp32 -> half): 128x128 floats = 4096 float4, 16 per thread
#pragma unroll
    for (int i = 0; i < 16; i++) {
        int lin = i * 256 + tid;
        int n = lin >> 5, c = (lin & 31) * 4;
        float4 v = *(const float4*)&W[n * 128 + c];
        __half2 h0 = __floats2half2_rn(v.x, v.y);
        __half2 h1 = __floats2half2_rn(v.z, v.w);
        uint2 t;
        t.x = *(uint32_t*)&h0; t.y = *(uint32_t*)&h1;
        *(uint2*)&Ws[n * HS + c] = t;
    }
    __syncthreads();

    float acc[2][8][4];
#pragma unroll
    for (int mt = 0; mt < 2; mt++)
#pragma unroll
        for (int nt = 0; nt < 8; nt++)
#pragma unroll
            for (int i = 0; i < 4; i++) acc[mt][nt][i] = 0.f;

#pragma unroll
    for (int ks = 0; ks < 8; ks++) {
        int k0 = ks * 16;
        uint32_t a[2][4];
#pragma unroll
        for (int mt = 0; mt < 2; mt++) {
            int r = warpM * 32 + mt * 16 + group;
            a[mt][0] = *(uint32_t*)&As[r * HS + k0 + 2 * tig];
            a[mt][1] = *(uint32_t*)&As[(r + 8) * HS + k0 + 2 * tig];
            a[mt][2] = *(uint32_t*)&As[r * HS + k0 + 8 + 2 * tig];
            a[mt][3] = *(uint32_t*)&As[(r + 8) * HS + k0 + 8 + 2 * tig];
        }
#pragma unroll
        for (int nt = 0; nt < 8; nt++) {
            int n = warpN * 64 + nt * 8 + group;
            uint32_t b0 = *(uint32_t*)&Ws[n * HS + k0 + 2 * tig];
            uint32_t b1 = *(uint32_t*)&Ws[n * HS + k0 + 8 + 2 * tig];
            mma_f16(acc[0][nt], a[0], b0, b1);
            mma_f16(acc[1][nt], a[1], b0, b1);
        }
    }
    // epilogue: fp32 acc -> optional dinv/bias -> half2 store
#pragma unroll
    for (int mt = 0; mt < 2; mt++) {
#pragma unroll
        for (int hh = 0; hh < 2; hh++) {
            int m = m0 + warpM * 32 + mt * 16 + group + hh * 8;
            if (m < M) {
                float rs = useDinv ? g_dinv[m] : 1.0f;
#pragma unroll
                for (int nt = 0; nt < 8; nt++) {
                    int n = warpN * 64 + nt * 8 + tig * 2;
                    float v0 = acc[mt][nt][hh * 2 + 0] * rs;
                    float v1 = acc[mt][nt][hh * 2 + 1] * rs;
                    if (bias) { v0 += bias[n]; v1 += bias[n + 1]; }
                    __half2 hv = __floats2half2_rn(v0, v1);
                    *(uint32_t*)&C[m * 128 + n] = *(uint32_t*)&hv;
                }
            }
        }
    }
}

// ---------------- CSR aggregation (half): out[i]=relu(dinv[i]*(sum g[j] + g[i]) + b) -----
__global__ __launch_bounds__(256)
void agg_kernel(int srcSel, int dstSel, const float* __restrict__ bias, int doRelu) {
    const __half* g = hsel(srcSel);
    __half* out = hsel(dstSel);
    int warp = (blockIdx.x * blockDim.x + threadIdx.x) >> 5;
    int lane = threadIdx.x & 31;
    if (warp >= N_NODES) return;
    int i = warp;
    int s = g_colptr[i], e = g_colptr[i + 1];
    const uint2* g2 = (const uint2*)g;   // 4 halves per lane (8B)

    float a0, a1, a2, a3;
    {   // self term
        uint2 v = g2[i * 32 + lane];
        float2 f0 = __half22float2(*(__half2*)&v.x);
        float2 f1 = __half22float2(*(__half2*)&v.y);
        a0 = f0.x; a1 = f0.y; a2 = f1.x; a3 = f1.y;
    }
    int t = s;
    for (; t + 4 <= e; t += 4) {
        int j0 = g_csr[t], j1 = g_csr[t + 1], j2 = g_csr[t + 2], j3 = g_csr[t + 3];
        uint2 v0 = g2[j0 * 32 + lane];
        uint2 v1 = g2[j1 * 32 + lane];
        uint2 v2 = g2[j2 * 32 + lane];
        uint2 v3 = g2[j3 * 32 + lane];
        float2 p;
        p = __half22float2(*(__half2*)&v0.x); a0 += p.x; a1 += p.y;
        p = __half22float2(*(__half2*)&v0.y); a2 += p.x; a3 += p.y;
        p = __half22float2(*(__half2*)&v1.x); a0 += p.x; a1 += p.y;
        p = __half22float2(*(__half2*)&v1.y); a2 += p.x; a3 += p.y;
        p = __half22float2(*(__half2*)&v2.x); a0 += p.x; a1 += p.y;
        p = __half22float2(*(__half2*)&v2.y); a2 += p.x; a3 += p.y;
        p = __half22float2(*(__half2*)&v3.x); a0 += p.x; a1 += p.y;
        p = __half22float2(*(__half2*)&v3.y); a2 += p.x; a3 += p.y;
    }
    for (; t < e; t++) {
        uint2 v = g2[g_csr[t] * 32 + lane];
        float2 p;
        p = __half22float2(*(__half2*)&v.x); a0 += p.x; a1 += p.y;
        p = __half22float2(*(__half2*)&v.y); a2 += p.x; a3 += p.y;
    }
    float di = g_dinv[i];
    float4 b4 = *(const float4*)&bias[lane * 4];
    a0 = a0 * di + b4.x;
    a1 = a1 * di + b4.y;
    a2 = a2 * di + b4.z;
    a3 = a3 * di + b4.w;
    if (doRelu) {
        a0 = fmaxf(a0, 0.f); a1 = fmaxf(a1, 0.f);
        a2 = fmaxf(a2, 0.f); a3 = fmaxf(a3, 0.f);
    }
    __half2 o0 = __floats2half2_rn(a0, a1);
    __half2 o1 = __floats2half2_rn(a2, a3);
    uint2 ov;
    ov.x = *(uint32_t*)&o0; ov.y = *(uint32_t*)&o1;
    ((uint2*)out)[i * 32 + lane] = ov;
}

// ---------------- pooling: one block per graph, fused divide ----------------
__global__ void pool_kernel() {
    __shared__ float s[256];
    const __half* h = g_h0;
    int g = blockIdx.x;
    int tid = threadIdx.x;
    int f = tid & 127, hh = tid >> 7;
    int gs = g_gstart[g], ge = g_gstart[g + 1];
    float acc = 0.f;
    for (int n = gs + hh; n < ge; n += 2)
        acc += __half2float(h[n * F + f]);
    s[tid] = acc;
    __syncthreads();
    if (hh == 0) {
        float cnt = (float)(ge - gs);
        float tot = s[tid] + s[tid + 128];
        g_concat[g * 192 + f] = tot / fmaxf(cnt, 1.0f);
    }
}

// ---------------- generic small GEMM (fp32): C[M,N] = act(A @ W^T + b) ----------------
__global__ __launch_bounds__(256)
void small_gemm(const float* __restrict__ Aext, int aSel, int aOff, int lda,
                const float* __restrict__ W, const float* __restrict__ bias,
                float* __restrict__ Cext, int cSel, int cOff, int ldc,
                int M, int N, int K, int doRelu) {
    const float* A = (Aext ? Aext : fsel(aSel) + aOff);
    float* C = (Cext ? Cext : fsel(cSel) + cOff);

    __shared__ __align__(16) float As[64][33];
    __shared__ __align__(16) float Ws2[32][68];
    int tid = threadIdx.x;
    int tx = tid & 15, ty = tid >> 4;
    int n0 = blockIdx.x * 64, m0 = blockIdx.y * 64;

    float acc[4][4];
#pragma unroll
    for (int i = 0; i < 4; i++)
#pragma unroll
        for (int j = 0; j < 4; j++) acc[i][j] = 0.f;

    for (int kc = 0; kc < K; kc += 32) {
#pragma unroll
        for (int j = 0; j < 8; j++) {
            int lin = j * 256 + tid;
            int m = lin >> 5, k = lin & 31;
            As[m][k] = (m0 + m < M) ? A[(m0 + m) * lda + kc + k] : 0.f;
        }
#pragma unroll
        for (int j = 0; j < 8; j++) {
            int lin = j * 256 + tid;
            int n = lin >> 5, k = lin & 31;
            Ws2[k][n] = (n0 + n < N) ? W[(n0 + n) * K + kc + k] : 0.f;
        }
        __syncthreads();
#pragma unroll
        for (int k = 0; k < 32; k++) {
            float aa[4];
#pragma unroll
            for (int i = 0; i < 4; i++) aa[i] = As[ty * 4 + i][k];
            float4 b = *(const float4*)&Ws2[k][tx * 4];
            float bb[4] = {b.x, b.y, b.z, b.w};
#pragma unroll
            for (int i = 0; i < 4; i++)
#pragma unroll
                for (int j = 0; j < 4; j++) acc[i][j] += aa[i] * bb[j];
        }
        __syncthreads();
    }
#pragma unroll
    for (int i = 0; i < 4; i++) {
        int m = m0 + ty * 4 + i;
        if (m < M) {
#pragma unroll
            for (int j = 0; j < 4; j++) {
                int n = n0 + tx * 4 + j;
                if (n < N) {
                    float v = acc[i][j];
                    if (bias) v += bias[n];
                    if (doRelu) v = fmaxf(v, 0.f);
                    C[m * ldc + n] = v;
                }
            }
        }
    }
}

// ---------------- launch ----------------
extern "C" void kernel_launch(void* const* d_in, const int* in_sizes, int n_in,
                              void* d_out, int out_size) {
    const float* x         = (const float*)d_in[0];
    const int*   ei        = (const int*)d_in[1];
    const int*   batch     = (const int*)d_in[2];
    const float* mol       = (const float*)d_in[3];
    const float* gcn_W     = (const float*)d_in[4];
    const float* gcn_b     = (const float*)d_in[5];
    const float* gcn_out_W = (const float*)d_in[6];
    const float* gcn_out_b = (const float*)d_in[7];
    const float* mlp_W     = (const float*)d_in[8];
    const float* mlp_b     = (const float*)d_in[9];
    const float* mlp_out_W = (const float*)d_in[10];
    const float* mlp_out_b = (const float*)d_in[11];
    const float* pred_W1   = (const float*)d_in[12];
    const float* pred_b1   = (const float*)d_in[13];
    const float* pred_W2   = (const float*)d_in[14];
    const float* pred_b2   = (const float*)d_in[15];
    const float* out_W     = (const float*)d_in[16];
    const float* out_b     = (const float*)d_in[17];
    float* out = (float*)d_out;

    cudaFuncSetAttribute(gemm_f16, cudaFuncAttributeMaxDynamicSharedMemorySize, GEMM_SMEM);

    const int GB = (N_NODES + 127) / 128;       // 391
    const int AB = (N_NODES * 32 + 255) / 256;  // 6250

    // preprocessing; gemm1 placed at launch #4 so the profiler slot captures it
    init_kernel<<<196, 256>>>();
    degree_kernel<<<3125, 256>>>(ei + N_EDGES);
    dinv_kernel<<<196, 256>>>();
    gemm_f16<<<GB, 256, GEMM_SMEM>>>(x, -1, gcn_W, 0, nullptr, 1, N_NODES);  // x -> g_h0
    scanA_kernel<<<NB, 256>>>();
    scanB_kernel<<<1, NB>>>();
    scanC_kernel<<<NB, 256>>>();
    csr_fill_kernel<<<3125, 256>>>(ei, ei + N_EDGES);
    counts_kernel<<<196, 256>>>(batch);
    gstart_kernel<<<1, 256>>>();

    // GCN layers (activations in half: 0 = g_h0, 1 = g_h1)
    agg_kernel<<<AB, 256>>>(0, 1, gcn_b, 1);
    gemm_f16<<<GB, 256, GEMM_SMEM>>>(nullptr, 1, gcn_W + 128 * 128, 0, nullptr, 1, N_NODES);
    agg_kernel<<<AB, 256>>>(0, 1, gcn_b + 128, 1);
    gemm_f16<<<GB, 256, GEMM_SMEM>>>(nullptr, 1, gcn_W + 2 * 128 * 128, 0, nullptr, 1, N_NODES);
    agg_kernel<<<AB, 256>>>(0, 1, gcn_b + 256, 1);
    gemm_f16<<<GB, 256, GEMM_SMEM>>>(nullptr, 1, gcn_out_W, 0, gcn_out_b, 0, N_NODES);

    // mean pool (fused divide) -> g_concat[:, 0:128]
    pool_kernel<<<N_GRAPHS, 256>>>();

    // MLP branch -> g_concat[:, 128:192]   (fsel: 2=concat, 3=s0, 4=s1)
    small_gemm<<<dim3(4, 4), 256>>>(mol, -1, 0, 256, mlp_W,         mlp_b,       nullptr, 3, 0, 256, 256, 256, 256, 1);
    small_gemm<<<dim3(4, 4), 256>>>(nullptr, 3, 0, 256, mlp_W + 65536, mlp_b + 256, nullptr, 4, 0, 256, 256, 256, 256, 1);
    small_gemm<<<dim3(1, 4), 256>>>(nullptr, 4, 0, 256, mlp_out_W,  mlp_out_b,   nullptr, 2, 128, 192, 256, 64, 256, 1);

    // prediction head
    small_gemm<<<dim3(4, 4), 256>>>(nullptr, 2, 0, 192, pred_W1, pred_b1, nullptr, 3, 0, 256, 256, 256, 192, 1);
    small_gemm<<<dim3(4, 4), 256>>>(nullptr, 3, 0, 256, pred_W2, pred_b2, nullptr, 4, 0, 256, 256, 256, 256, 1);
    small_gemm<<<dim3(1, 4), 256>>>(nullptr, 4, 0, 256, out_W,   out_b,   out,     0, 0, 1,   256, 1,   256, 0);
}

// round 6
// speedup vs baseline: 3.3711x; 1.2273x over previous
#include <cuda_runtime.h>
#include <cuda_fp16.h>
#include <math.h>
#include <stdint.h>

#define N_NODES  50000
#define N_EDGES  800000
#define N_GRAPHS 256
#define F        128
#define NB       256   // scan blocks
#define CH       196   // nodes per scan block (256*196 >= 50000)

// ---------------- scratch (static __device__ — no allocation anywhere) ----------------
__device__ __half g_h0[N_NODES * F];
__device__ __half g_h1[N_NODES * F];
__device__ float  g_dinv[N_NODES];
__device__ int    g_deg[N_NODES];
__device__ int    g_colptr[N_NODES + 1];
__device__ int    g_cursor[N_NODES];
__device__ int    g_csr[N_EDGES];
__device__ int    g_part[NB];
__device__ int    g_poff[NB];
__device__ int    g_counti[N_GRAPHS];
__device__ int    g_gstart[N_GRAPHS + 1];
__device__ float  g_concat[N_GRAPHS * 192];
__device__ float  g_s0[N_GRAPHS * 256];
__device__ float  g_s1[N_GRAPHS * 256];

__device__ __forceinline__ __half* hsel(int s) { return s == 0 ? g_h0 : g_h1; }
__device__ __forceinline__ float* fsel(int s) {
    switch (s) { case 2: return g_concat; case 3: return g_s0; default: return g_s1; }
}

// ---------------- init ----------------
__global__ void init_kernel() {
    int i = blockIdx.x * blockDim.x + threadIdx.x;
    if (i < N_NODES)  g_deg[i] = 0;
    if (i < N_GRAPHS) g_counti[i] = 0;
}

// ---------------- degree histogram + per-graph counts (fused) ----------------
__global__ void degcnt_kernel(const int* __restrict__ col, const int* __restrict__ batch) {
    int e = blockIdx.x * blockDim.x + threadIdx.x;
    if (e < N_EDGES) atomicAdd(&g_deg[col[e]], 1);
    if (e < N_NODES) atomicAdd(&g_counti[batch[e]], 1);
}

// ---------------- 3-phase parallel scan of degrees -> colptr/cursor (+dinv) -------------
__global__ void scanA_kernel() {           // per-block partial sums
    __shared__ int s[256];
    int t = threadIdx.x, b = blockIdx.x;
    int i = b * CH + t;
    int v = (t < CH && i < N_NODES) ? g_deg[i] : 0;
    s[t] = v;
    __syncthreads();
    for (int off = 128; off > 0; off >>= 1) {
        if (t < off) s[t] += s[t + off];
        __syncthreads();
    }
    if (t == 0) g_part[b] = s[0];
}
__global__ void scanB_kernel() {           // scan the 256 partials
    __shared__ int s[NB];
    int t = threadIdx.x;
    int mine = g_part[t];
    s[t] = mine;
    __syncthreads();
    for (int off = 1; off < NB; off <<= 1) {
        int v = (t >= off) ? s[t - off] : 0;
        __syncthreads();
        s[t] += v;
        __syncthreads();
    }
    g_poff[t] = s[t] - mine;               // exclusive
    if (t == 0) g_colptr[N_NODES] = N_EDGES;
}
__global__ void scanC_kernel() {           // per-block exclusive scan + offset + dinv
    __shared__ int s[256];
    int t = threadIdx.x, b = blockIdx.x;
    int i = b * CH + t;
    int d = (t < CH && i < N_NODES) ? g_deg[i] : 0;
    s[t] = d;
    __syncthreads();
    for (int off = 1; off < 256; off <<= 1) {
        int v = (t >= off) ? s[t - off] : 0;
        __syncthreads();
        s[t] += v;
        __syncthreads();
    }
    if (t < CH && i < N_NODES) {
        int cp = g_poff[b] + s[t] - d;
        g_colptr[i] = cp;
        g_cursor[i] = cp;
        g_dinv[i]   = rsqrtf((float)d + 1.0f);
    }
}

// ---------------- CSR fill ----------------
__global__ void csr_fill_kernel(const int* __restrict__ row,
                                const int* __restrict__ col) {
    int e = blockIdx.x * blockDim.x + threadIdx.x;
    if (e < N_EDGES) {
        int c = col[e];
        int pos = atomicAdd(&g_cursor[c], 1);
        g_csr[pos] = row[e];
    }
}

// ---------------- graph boundaries ----------------
__global__ void gstart_kernel() {          // 1 block, 256 threads
    __shared__ int s[N_GRAPHS];
    int t = threadIdx.x;
    s[t] = g_counti[t];
    __syncthreads();
    for (int off = 1; off < N_GRAPHS; off <<= 1) {
        int v = (t >= off) ? s[t - off] : 0;
        __syncthreads();
        s[t] += v;
        __syncthreads();
    }
    g_gstart[t + 1] = s[t];
    if (t == 0) g_gstart[0] = 0;
}

// ---------------- fp16 MMA helpers ----------------
__device__ __forceinline__ void mma_f16(float (&c)[4], const uint32_t (&a)[4],
                                        uint32_t b0, uint32_t b1) {
    asm("mma.sync.aligned.m16n8k16.row.col.f32.f16.f16.f32 "
        "{%0,%1,%2,%3},{%4,%5,%6,%7},{%8,%9},{%0,%1,%2,%3};"
        : "+f"(c[0]), "+f"(c[1]), "+f"(c[2]), "+f"(c[3])
        : "r"(a[0]), "r"(a[1]), "r"(a[2]), "r"(a[3]), "r"(b0), "r"(b1));
}

// ---------------- fp16 tensor-core GEMM: C[M,128] = A[M,128] @ W[128,128]^T -------------
#define HS 136
#define GEMM_SMEM (2 * 128 * HS * 2)
__global__ __launch_bounds__(256)
void gemm_f16(const float* __restrict__ Aext, int aSel,
              const float* __restrict__ W, int cSel,
              const float* __restrict__ bias, int M) {
    extern __shared__ __half sh[];
    __half* As = sh;              // [128][HS]
    __half* Ws = sh + 128 * HS;   // [128][HS]
    __half* C = hsel(cSel);

    int tid = threadIdx.x;
    int wid = tid >> 5, lane = tid & 31;
    int group = lane >> 2, tig = lane & 3;
    int warpM = wid & 3, warpN = wid >> 2;
    int m0 = blockIdx.x * 128;

    if (Aext) {
#pragma unroll
        for (int i = 0; i < 8; i++) {
            int lin = i * 256 + tid;
            int r = lin >> 4, c = (lin & 15) * 8;
            float4 v0 = make_float4(0.f, 0.f, 0.f, 0.f), v1 = v0;
            if (m0 + r < M) {
                v0 = *(const float4*)&Aext[(m0 + r) * 128 + c];
                v1 = *(const float4*)&Aext[(m0 + r) * 128 + c + 4];
            }
            __half2 h0 = __floats2half2_rn(v0.x, v0.y);
            __half2 h1 = __floats2half2_rn(v0.z, v0.w);
            __half2 h2 = __floats2half2_rn(v1.x, v1.y);
            __half2 h3 = __floats2half2_rn(v1.z, v1.w);
            uint4 t;
            t.x = *(uint32_t*)&h0; t.y = *(uint32_t*)&h1;
            t.z = *(uint32_t*)&h2; t.w = *(uint32_t*)&h3;
            *(uint4*)&As[r * HS + c] = t;
        }
    } else {
        const __half* A = hsel(aSel);
#pragma unroll
        for (int i = 0; i < 8; i++) {
            int lin = i * 256 + tid;
            int r = lin >> 4, c = (lin & 15) * 8;
            uint4 t = make_uint4(0, 0, 0, 0);
            if (m0 + r < M) t = *(const uint4*)&A[(m0 + r) * 128 + c];
            *(uint4*)&As[r * HS + c] = t;
        }
    }
#pragma unroll
    for (int i = 0; i < 16; i++) {
        int lin = i * 256 + tid;
        int n = lin >> 5, c = (lin & 31) * 4;
        float4 v = *(const float4*)&W[n * 128 + c];
        __half2 h0 = __floats2half2_rn(v.x, v.y);
        __half2 h1 = __floats2half2_rn(v.z, v.w);
        uint2 t;
        t.x = *(uint32_t*)&h0; t.y = *(uint32_t*)&h1;
        *(uint2*)&Ws[n * HS + c] = t;
    }
    __syncthreads();

    float acc[2][8][4];
#pragma unroll
    for (int mt = 0; mt < 2; mt++)
#pragma unroll
        for (int nt = 0; nt < 8; nt++)
#pragma unroll
            for (int i = 0; i < 4; i++) acc[mt][nt][i] = 0.f;

#pragma unroll
    for (int ks = 0; ks < 8; ks++) {
        int k0 = ks * 16;
        uint32_t a[2][4];
#pragma unroll
        for (int mt = 0; mt < 2; mt++) {
            int r = warpM * 32 + mt * 16 + group;
            a[mt][0] = *(uint32_t*)&As[r * HS + k0 + 2 * tig];
            a[mt][1] = *(uint32_t*)&As[(r + 8) * HS + k0 + 2 * tig];
            a[mt][2] = *(uint32_t*)&As[r * HS + k0 + 8 + 2 * tig];
            a[mt][3] = *(uint32_t*)&As[(r + 8) * HS + k0 + 8 + 2 * tig];
        }
#pragma unroll
        for (int nt = 0; nt < 8; nt++) {
            int n = warpN * 64 + nt * 8 + group;
            uint32_t b0 = *(uint32_t*)&Ws[n * HS + k0 + 2 * tig];
            uint32_t b1 = *(uint32_t*)&Ws[n * HS + k0 + 8 + 2 * tig];
            mma_f16(acc[0][nt], a[0], b0, b1);
            mma_f16(acc[1][nt], a[1], b0, b1);
        }
    }
#pragma unroll
    for (int mt = 0; mt < 2; mt++) {
#pragma unroll
        for (int hh = 0; hh < 2; hh++) {
            int m = m0 + warpM * 32 + mt * 16 + group + hh * 8;
            if (m < M) {
#pragma unroll
                for (int nt = 0; nt < 8; nt++) {
                    int n = warpN * 64 + nt * 8 + tig * 2;
                    float v0 = acc[mt][nt][hh * 2 + 0];
                    float v1 = acc[mt][nt][hh * 2 + 1];
                    if (bias) { v0 += bias[n]; v1 += bias[n + 1]; }
                    __half2 hv = __floats2half2_rn(v0, v1);
                    *(uint32_t*)&C[m * 128 + n] = *(uint32_t*)&hv;
                }
            }
        }
    }
}

// ---------------- CSR aggregation (half, uint4, 2 edges in flight per warp) --------------
// out[i] = relu(dinv[i] * (sum_j g[j]*dinv[j] + g[i]*dinv[i]) + b)
__device__ __forceinline__ void acc_row(float (&a)[8], uint4 v, float sc) {
    float2 p;
    p = __half22float2(*(__half2*)&v.x); a[0] += p.x * sc; a[1] += p.y * sc;
    p = __half22float2(*(__half2*)&v.y); a[2] += p.x * sc; a[3] += p.y * sc;
    p = __half22float2(*(__half2*)&v.z); a[4] += p.x * sc; a[5] += p.y * sc;
    p = __half22float2(*(__half2*)&v.w); a[6] += p.x * sc; a[7] += p.y * sc;
}

__global__ __launch_bounds__(256)
void agg_kernel(int srcSel, int dstSel, const float* __restrict__ bias, int doRelu) {
    const __half* g = hsel(srcSel);
    __half* out = hsel(dstSel);
    int warp = (blockIdx.x * blockDim.x + threadIdx.x) >> 5;
    int lane = threadIdx.x & 31;
    if (warp >= N_NODES) return;
    int i = warp;
    int half = lane >> 4, li = lane & 15;
    int s = g_colptr[i], e = g_colptr[i + 1];
    const uint4* g4 = (const uint4*)g;   // row = 16 uint4 (256B)

    float di = g_dinv[i];
    float acc[8];
#pragma unroll
    for (int k = 0; k < 8; k++) acc[k] = 0.f;
    if (half == 0) {              // self term: g[i]*dinv[i]
        uint4 v = g4[i * 16 + li];
        acc_row(acc, v, di);
    }
    int t = s + half;
    for (; t + 2 < e; t += 4) {   // 2 edges per half-warp iteration
        int j0 = g_csr[t], j1 = g_csr[t + 2];
        float d0 = g_dinv[j0], d1 = g_dinv[j1];
        uint4 v0 = g4[j0 * 16 + li];
        uint4 v1 = g4[j1 * 16 + li];
        acc_row(acc, v0, d0);
        acc_row(acc, v1, d1);
    }
    for (; t < e; t += 2) {
        int j = g_csr[t];
        float dj = g_dinv[j];
        uint4 v = g4[j * 16 + li];
        acc_row(acc, v, dj);
    }
#pragma unroll
    for (int k = 0; k < 8; k++)
        acc[k] += __shfl_down_sync(0xffffffffu, acc[k], 16);
    if (half == 0) {
        float4 b0 = *(const float4*)&bias[li * 8];
        float4 b1 = *(const float4*)&bias[li * 8 + 4];
        float r[8];
        r[0] = acc[0] * di + b0.x; r[1] = acc[1] * di + b0.y;
        r[2] = acc[2] * di + b0.z; r[3] = acc[3] * di + b0.w;
        r[4] = acc[4] * di + b1.x; r[5] = acc[5] * di + b1.y;
        r[6] = acc[6] * di + b1.z; r[7] = acc[7] * di + b1.w;
        if (doRelu) {
#pragma unroll
            for (int k = 0; k < 8; k++) r[k] = fmaxf(r[k], 0.f);
        }
        __half2 h0 = __floats2half2_rn(r[0], r[1]);
        __half2 h1 = __floats2half2_rn(r[2], r[3]);
        __half2 h2 = __floats2half2_rn(r[4], r[5]);
        __half2 h3 = __floats2half2_rn(r[6], r[7]);
        uint4 ov;
        ov.x = *(uint32_t*)&h0; ov.y = *(uint32_t*)&h1;
        ov.z = *(uint32_t*)&h2; ov.w = *(uint32_t*)&h3;
        ((uint4*)out)[i * 16 + li] = ov;
    }
}

// ---------------- pooling: one block per graph, fused divide ----------------
__global__ void pool_kernel() {
    __shared__ float s[256];
    const __half* h = g_h0;
    int g = blockIdx.x;
    int tid = threadIdx.x;
    int f = tid & 127, hh = tid >> 7;
    int gs = g_gstart[g], ge = g_gstart[g + 1];
    float acc = 0.f;
    for (int n = gs + hh; n < ge; n += 2)
        acc += __half2float(h[n * F + f]);
    s[tid] = acc;
    __syncthreads();
    if (hh == 0) {
        float cnt = (float)(ge - gs);
        float tot = s[tid] + s[tid + 128];
        g_concat[g * 192 + f] = tot / fmaxf(cnt, 1.0f);
    }
}

// ---------------- generic small GEMM (fp32): C[M,N] = act(A @ W^T + b) ----------------
__global__ __launch_bounds__(256)
void small_gemm(const float* __restrict__ Aext, int aSel, int aOff, int lda,
                const float* __restrict__ W, const float* __restrict__ bias,
                float* __restrict__ Cext, int cSel, int cOff, int ldc,
                int M, int N, int K, int doRelu) {
    const float* A = (Aext ? Aext : fsel(aSel) + aOff);
    float* C = (Cext ? Cext : fsel(cSel) + cOff);

    __shared__ __align__(16) float As[64][33];
    __shared__ __align__(16) float Ws2[32][68];
    int tid = threadIdx.x;
    int tx = tid & 15, ty = tid >> 4;
    int n0 = blockIdx.x * 64, m0 = blockIdx.y * 64;

    float acc[4][4];
#pragma unroll
    for (int i = 0; i < 4; i++)
#pragma unroll
        for (int j = 0; j < 4; j++) acc[i][j] = 0.f;

    for (int kc = 0; kc < K; kc += 32) {
#pragma unroll
        for (int j = 0; j < 8; j++) {
            int lin = j * 256 + tid;
            int m = lin >> 5, k = lin & 31;
            As[m][k] = (m0 + m < M) ? A[(m0 + m) * lda + kc + k] : 0.f;
        }
#pragma unroll
        for (int j = 0; j < 8; j++) {
            int lin = j * 256 + tid;
            int n = lin >> 5, k = lin & 31;
            Ws2[k][n] = (n0 + n < N) ? W[(n0 + n) * K + kc + k] : 0.f;
        }
        __syncthreads();
#pragma unroll
        for (int k = 0; k < 32; k++) {
            float aa[4];
#pragma unroll
            for (int i = 0; i < 4; i++) aa[i] = As[ty * 4 + i][k];
            float4 b = *(const float4*)&Ws2[k][tx * 4];
            float bb[4] = {b.x, b.y, b.z, b.w};
#pragma unroll
            for (int i = 0; i < 4; i++)
#pragma unroll
                for (int j = 0; j < 4; j++) acc[i][j] += aa[i] * bb[j];
        }
        __syncthreads();
    }
#pragma unroll
    for (int i = 0; i < 4; i++) {
        int m = m0 + ty * 4 + i;
        if (m < M) {
#pragma unroll
            for (int j = 0; j < 4; j++) {
                int n = n0 + tx * 4 + j;
                if (n < N) {
                    float v = acc[i][j];
                    if (bias) v += bias[n];
                    if (doRelu) v = fmaxf(v, 0.f);
                    C[m * ldc + n] = v;
                }
            }
        }
    }
}

// ---------------- launch ----------------
extern "C" void kernel_launch(void* const* d_in, const int* in_sizes, int n_in,
                              void* d_out, int out_size) {
    const float* x         = (const float*)d_in[0];
    const int*   ei        = (const int*)d_in[1];
    const int*   batch     = (const int*)d_in[2];
    const float* mol       = (const float*)d_in[3];
    const float* gcn_W     = (const float*)d_in[4];
    const float* gcn_b     = (const float*)d_in[5];
    const float* gcn_out_W = (const float*)d_in[6];
    const float* gcn_out_b = (const float*)d_in[7];
    const float* mlp_W     = (const float*)d_in[8];
    const float* mlp_b     = (const float*)d_in[9];
    const float* mlp_out_W = (const float*)d_in[10];
    const float* mlp_out_b = (const float*)d_in[11];
    const float* pred_W1   = (const float*)d_in[12];
    const float* pred_b1   = (const float*)d_in[13];
    const float* pred_W2   = (const float*)d_in[14];
    const float* pred_b2   = (const float*)d_in[15];
    const float* out_W     = (const float*)d_in[16];
    const float* out_b     = (const float*)d_in[17];
    float* out = (float*)d_out;

    // one-time host infra (streams/events are host objects, no device memory)
    static cudaStream_t sP = 0, sM = 0;
    static cudaEvent_t evRoot = 0, evP = 0, evM = 0;
    if (!sP) {
        cudaStreamCreateWithFlags(&sP, cudaStreamNonBlocking);
        cudaStreamCreateWithFlags(&sM, cudaStreamNonBlocking);
        cudaEventCreateWithFlags(&evRoot, cudaEventDisableTiming);
        cudaEventCreateWithFlags(&evP, cudaEventDisableTiming);
        cudaEventCreateWithFlags(&evM, cudaEventDisableTiming);
        cudaFuncSetAttribute(gemm_f16, cudaFuncAttributeMaxDynamicSharedMemorySize, GEMM_SMEM);
    }

    const int GB = (N_NODES + 127) / 128;       // 391
    const int AB = (N_NODES * 32 + 255) / 256;  // 6250

    // ---- fork ----
    cudaEventRecord(evRoot, 0);
    cudaStreamWaitEvent(sP, evRoot, 0);
    cudaStreamWaitEvent(sM, evRoot, 0);

    // stream P: graph preprocessing (only needs edge_index / batch_index)
    init_kernel<<<196, 256, 0, sP>>>();
    degcnt_kernel<<<3125, 256, 0, sP>>>(ei + N_EDGES, batch);
    scanA_kernel<<<NB, 256, 0, sP>>>();
    scanB_kernel<<<1, NB, 0, sP>>>();
    scanC_kernel<<<NB, 256, 0, sP>>>();
    csr_fill_kernel<<<3125, 256, 0, sP>>>(ei, ei + N_EDGES);
    gstart_kernel<<<1, 256, 0, sP>>>();
    cudaEventRecord(evP, sP);

    // stream M: MLP branch (only needs mol_features) -> g_concat[:, 128:192]
    small_gemm<<<dim3(4, 4), 256, 0, sM>>>(mol, -1, 0, 256, mlp_W,         mlp_b,       nullptr, 3, 0, 256, 256, 256, 256, 1);
    small_gemm<<<dim3(4, 4), 256, 0, sM>>>(nullptr, 3, 0, 256, mlp_W + 65536, mlp_b + 256, nullptr, 4, 0, 256, 256, 256, 256, 1);
    small_gemm<<<dim3(1, 4), 256, 0, sM>>>(nullptr, 4, 0, 256, mlp_out_W,  mlp_out_b,   nullptr, 2, 128, 192, 256, 64, 256, 1);
    cudaEventRecord(evM, sM);

    // main stream: gemm1 (x -> g_h0), no dinv dependency (dinv folded into agg)
    gemm_f16<<<GB, 256, GEMM_SMEM>>>(x, -1, gcn_W, 0, nullptr, N_NODES);

    // join preprocessing, then GCN layer chain (ping-pong h0/h1)
    cudaStreamWaitEvent(0, evP, 0);
    agg_kernel<<<AB, 256>>>(0, 1, gcn_b, 1);
    gemm_f16<<<GB, 256, GEMM_SMEM>>>(nullptr, 1, gcn_W + 128 * 128, 0, nullptr, N_NODES);
    agg_kernel<<<AB, 256>>>(0, 1, gcn_b + 128, 1);
    gemm_f16<<<GB, 256, GEMM_SMEM>>>(nullptr, 1, gcn_W + 2 * 128 * 128, 0, nullptr, N_NODES);
    agg_kernel<<<AB, 256>>>(0, 1, gcn_b + 256, 1);
    gemm_f16<<<GB, 256, GEMM_SMEM>>>(nullptr, 1, gcn_out_W, 0, gcn_out_b, N_NODES);

    // mean pool (fused divide) -> g_concat[:, 0:128]
    pool_kernel<<<N_GRAPHS, 256>>>();

    // join MLP branch, then prediction head
    cudaStreamWaitEvent(0, evM, 0);
    small_gemm<<<dim3(4, 4), 256>>>(nullptr, 2, 0, 192, pred_W1, pred_b1, nullptr, 3, 0, 256, 256, 256, 192, 1);
    small_gemm<<<dim3(4, 4), 256>>>(nullptr, 3, 0, 256, pred_W2, pred_b2, nullptr, 4, 0, 256, 256, 256, 256, 1);
    small_gemm<<<dim3(1, 4), 256>>>(nullptr, 4, 0, 256, out_W,   out_b,   out,     0, 0, 1,   256, 1,   256, 0);
}